// round 3
// baseline (speedup 1.0000x reference)
#include <cuda_runtime.h>
#include <cuda_bf16.h>

// Problem geometry: [B=4, 1, D=160, H=160, W=160]
#define NB 4
#define S  160
#define PLANE      (S * S)          // 25600 elems per (b,d) plane
#define PLANE4     (PLANE / 4)      // 6400 float4/int4 per plane
#define HALF4      (PLANE4 / 2)     // 3200
#define NPLANES    (NB * S)         // 640
#define TOTAL_ELEMS (4.0 * 160.0 * 160.0 * 160.0)

// ---- device scratch (no allocations allowed) ----
__device__ unsigned char g_any[NB][3][S];  // axis projections: 0=D,1=H,2=W
__device__ int      g_lo[NB][3];
__device__ int      g_hi[NB][3];
__device__ int      g_fg[NB];
__device__ double   g_acc;
__device__ unsigned g_done_proj;
__device__ unsigned g_done_main;

// ---------------- kernel 0: zero scratch (every replay) ----------------
__global__ void k_init() {
    int t = blockIdx.x * blockDim.x + threadIdx.x;
    if (t == 0) { g_acc = 0.0; g_done_proj = 0u; g_done_main = 0u; }
    if (t < NB * 3 * S) ((unsigned char*)g_any)[t] = 0;
}

// ---------------- kernel 1: mask -> projections, last block -> bbox ---------
// One block per (b,d) plane, 400 threads. Thread owns FIXED int4-column
// c = tid%40 and row-group r = tid/40 (10 groups x 16 rows). W-axis OR lives
// in a register; one conditional shared byte store per 16B feeds H flags.
// Global flag stores are benign races (all writers store 1). The LAST block
// to finish (ticket) computes the bounding boxes (exact f32 reference math).
__global__ __launch_bounds__(400) void k_proj(const int* __restrict__ mask) {
    __shared__ int4 sCol[10][40];
    __shared__ unsigned char sH[S];
    __shared__ int sLast;

    const int bx  = blockIdx.x;          // 0..639
    const int b   = bx / S;
    const int d   = bx - b * S;
    const int tid = threadIdx.x;
    const int c   = tid % 40;
    const int r   = tid / 40;            // 0..9

    if (tid < S) sH[tid] = 0;
    __syncthreads();

    const int4* M = (const int4*)mask + (size_t)bx * PLANE4;

    int4 colOr = make_int4(0, 0, 0, 0);
    #pragma unroll 4
    for (int k = 0; k < 16; k++) {
        int h  = r + k * 10;
        int4 v = M[h * 40 + c];
        colOr.x |= v.x; colOr.y |= v.y; colOr.z |= v.z; colOr.w |= v.w;
        if (v.x | v.y | v.z | v.w) sH[h] = 1;
    }
    sCol[r][c] = colOr;
    int planeAny = __syncthreads_or(colOr.x | colOr.y | colOr.z | colOr.w);

    if (tid < 40) {
        int4 o = sCol[0][tid];
        #pragma unroll
        for (int r2 = 1; r2 < 10; r2++) {
            int4 v = sCol[r2][tid];
            o.x |= v.x; o.y |= v.y; o.z |= v.z; o.w |= v.w;
        }
        if (o.x) g_any[b][2][tid * 4 + 0] = 1;
        if (o.y) g_any[b][2][tid * 4 + 1] = 1;
        if (o.z) g_any[b][2][tid * 4 + 2] = 1;
        if (o.w) g_any[b][2][tid * 4 + 3] = 1;
    }
    if (tid < S && sH[tid]) g_any[b][1][tid] = 1;
    if (tid == 0 && planeAny) g_any[b][0][d] = 1;

    // ---- last-done block computes the bbox ----
    __threadfence();
    if (tid == 0) {
        unsigned ticket = atomicAdd(&g_done_proj, 1u);
        sLast = (ticket == (unsigned)(gridDim.x - 1));
    }
    __syncthreads();
    if (sLast && tid < NB * 3) {
        int bb = tid / 3;
        int ax = tid - bb * 3;
        volatile unsigned char* a = &g_any[bb][ax][0];
        int mn = -1, mx = -1;
        for (int i = 0; i < S; i++) {
            if (a[i]) { if (mn < 0) mn = i; mx = i; }
        }
        int fg = (mn >= 0);
        if (ax == 0) g_fg[bb] = fg;
        int lo = 0, hi = 0;
        if (fg) {
            float mnf = (float)mn, mxf = (float)mx;
            float ctr = (mxf + mnf) * 0.5f;
            float e   = (mxf - mnf + 1.0f) * 0.5f * 1.2f;     // EXPAND
            lo = (int)fmaxf(0.0f, floorf(ctr - e));
            hi = (int)fminf((float)(S - 1), floorf(ctr + e)); // EXCLUSIVE bound
        }
        g_lo[bb][ax] = lo;
        g_hi[bb][ax] = hi;
    }
}

// ---------------- kernel 2: weighted SSE reduction + finalize ----------------
// 1280 blocks x 256 threads, half-plane per block (3200 float4, 12.5 iters).
// launch_bounds(256,8) caps regs at 32 -> full 2048 thr/SM residency.
__global__ __launch_bounds__(256, 8) void k_main(const float* __restrict__ pred,
                                                 const float* __restrict__ truth,
                                                 float* __restrict__ out) {
    const int bx    = blockIdx.x;        // 0..1279
    const int plane = bx >> 1;
    const int half  = bx & 1;
    const int b     = plane / S;
    const int d     = plane - b * S;
    const int tid   = threadIdx.x;

    const int fg  = g_fg[b];
    const int loD = g_lo[b][0], hiD = g_hi[b][0];
    const int loH = g_lo[b][1], hiH = g_hi[b][1];
    const int loW = g_lo[b][2], hiW = g_hi[b][2];
    const bool inD = fg && (d >= loD) && (d < hiD);
    const unsigned hRange = (unsigned)(hiH - loH);
    const unsigned wRange = (unsigned)(hiW - loW);

    const float4* P = (const float4*)pred  + (size_t)plane * PLANE4 + half * HALF4;
    const float4* T = (const float4*)truth + (size_t)plane * PLANE4 + half * HALF4;
    const int hbase = half * 80;         // first h of this half-plane

    float acc = 0.0f;
    #pragma unroll 4
    for (int i = tid; i < HALF4; i += 256) {
        float4 p = P[i];
        float4 t = T[i];
        int h  = hbase + i / 40;
        int w0 = (i % 40) * 4;
        bool inH = inD && ((unsigned)(h - loH) < hRange);

        float wx = (inH && (unsigned)(w0 + 0 - loW) < wRange) ? 1.0f : 0.01f;
        float wy = (inH && (unsigned)(w0 + 1 - loW) < wRange) ? 1.0f : 0.01f;
        float wz = (inH && (unsigned)(w0 + 2 - loW) < wRange) ? 1.0f : 0.01f;
        float ww = (inH && (unsigned)(w0 + 3 - loW) < wRange) ? 1.0f : 0.01f;

        float dx = p.x - t.x, dy = p.y - t.y, dz = p.z - t.z, dw = p.w - t.w;
        acc = fmaf(wx * dx, dx, acc);
        acc = fmaf(wy * dy, dy, acc);
        acc = fmaf(wz * dz, dz, acc);
        acc = fmaf(ww * dw, dw, acc);
    }

    // warp reduce (float), then block reduce (double), one atomicAdd per block
    #pragma unroll
    for (int off = 16; off > 0; off >>= 1)
        acc += __shfl_xor_sync(0xFFFFFFFFu, acc, off);

    __shared__ double warpSum[8];
    int lane = tid & 31, wid = tid >> 5;
    if (lane == 0) warpSum[wid] = (double)acc;
    __syncthreads();
    if (tid == 0) {
        double s = 0.0;
        #pragma unroll
        for (int w = 0; w < 8; w++) s += warpSum[w];
        atomicAdd(&g_acc, s);
        __threadfence();
        unsigned ticket = atomicAdd(&g_done_main, 1u);
        if (ticket == gridDim.x - 1) {
            out[0] = (float)(g_acc / TOTAL_ELEMS);
        }
    }
}

extern "C" void kernel_launch(void* const* d_in, const int* in_sizes, int n_in,
                              void* d_out, int out_size) {
    const float* y_pred = (const float*)d_in[0];
    const float* y_true = (const float*)d_in[1];
    const int*   mask   = (const int*)d_in[2];
    float* out = (float*)d_out;

    k_init<<<2, 1024>>>();
    k_proj<<<NPLANES, 400>>>(mask);
    k_main<<<2 * NPLANES, 256>>>(y_pred, y_true, out);
}

// round 4
// speedup vs baseline: 1.0530x; 1.0530x over previous
#include <cuda_runtime.h>
#include <cuda_bf16.h>

// Problem geometry: [B=4, 1, D=160, H=160, W=160]
#define NB 4
#define S  160
#define PLANE   (S * S)            // 25600 elems per (b,d) plane
#define PLANE4  (PLANE / 4)        // 6400 float4/int4 per plane
#define NPLANES (NB * S)           // 640
#define N4      (NB * S * PLANE4)  // 4,096,000 float4 groups total
#define BATCH4  (S * PLANE4)       // 1,024,000 float4 per batch
#define TOTAL_ELEMS (4.0 * 160.0 * 160.0 * 160.0)

#define MAIN_BLOCKS (148 * 7)      // 1036: exactly one full wave at 7 blocks/SM

// ---- device scratch (zero at module load; k_main's last block re-zeroes
//      everything at the end of every execution, so each graph replay starts
//      from the same state — no init kernel needed) ----
__device__ unsigned char g_any[NB][3][S];  // axis projections: 0=D,1=H,2=W
__device__ int      g_lo[NB][3];
__device__ int      g_hi[NB][3];
__device__ double   g_acc;
__device__ unsigned g_done_proj;
__device__ unsigned g_done_main;

// ---------------- kernel 1: mask -> projections; last block -> bbox ---------
// One block per (b,d) plane, 320 threads (5 blocks/SM -> 740 slots >= 640:
// single wave). Thread owns FIXED int4-column c = tid%40, row-group r = tid/40
// (8 groups x 20 rows). W-axis OR lives in a register; one conditional shared
// byte store per 16B feeds the H flags. Global flag stores are benign races
// (all writers store 1). The LAST block (ticket) computes the bounding boxes
// with warp ballots (exact f32 replication of the reference math).
__global__ __launch_bounds__(320) void k_proj(const int* __restrict__ mask) {
    __shared__ int4 sCol[8][40];
    __shared__ unsigned char sH[S];
    __shared__ int sLast;

    const int bx  = blockIdx.x;          // 0..639
    const int b   = bx / S;
    const int d   = bx - b * S;
    const int tid = threadIdx.x;
    const int c   = tid % 40;
    const int r   = tid / 40;            // 0..7

    if (tid < S) sH[tid] = 0;
    __syncthreads();

    const int4* M = (const int4*)mask + (size_t)bx * PLANE4;

    int4 colOr = make_int4(0, 0, 0, 0);
    #pragma unroll 5
    for (int k = 0; k < 20; k++) {
        int h  = r + k * 8;
        int4 v = M[h * 40 + c];
        colOr.x |= v.x; colOr.y |= v.y; colOr.z |= v.z; colOr.w |= v.w;
        if (v.x | v.y | v.z | v.w) sH[h] = 1;
    }
    sCol[r][c] = colOr;
    int planeAny = __syncthreads_or(colOr.x | colOr.y | colOr.z | colOr.w);

    if (tid < 40) {
        int4 o = sCol[0][tid];
        #pragma unroll
        for (int r2 = 1; r2 < 8; r2++) {
            int4 v = sCol[r2][tid];
            o.x |= v.x; o.y |= v.y; o.z |= v.z; o.w |= v.w;
        }
        if (o.x) g_any[b][2][tid * 4 + 0] = 1;
        if (o.y) g_any[b][2][tid * 4 + 1] = 1;
        if (o.z) g_any[b][2][tid * 4 + 2] = 1;
        if (o.w) g_any[b][2][tid * 4 + 3] = 1;
    }
    if (tid < S && sH[tid]) g_any[b][1][tid] = 1;
    if (tid == 0 && planeAny) g_any[b][0][d] = 1;

    // ---- last-done block computes the 12 bounding-box axis ranges ----
    __threadfence();
    if (tid == 0) {
        unsigned ticket = atomicAdd(&g_done_proj, 1u);
        sLast = (ticket == (unsigned)(gridDim.x - 1));
    }
    __syncthreads();
    if (!sLast) return;
    __threadfence();

    const int wid  = tid >> 5;           // 0..9
    const int lane = tid & 31;
    for (int pair = wid; pair < NB * 3; pair += 10) {
        int bb = pair / 3;
        int ax = pair - bb * 3;
        volatile unsigned char* a = &g_any[bb][ax][0];
        int mn = -1, mx = -1;
        #pragma unroll
        for (int k = 0; k < 5; k++) {    // 5 ballots x 32 = 160 coords
            unsigned m = __ballot_sync(0xFFFFFFFFu, a[lane + 32 * k] != 0);
            if (m) {
                if (mn < 0) mn = 32 * k + __ffs(m) - 1;
                mx = 32 * k + 31 - __clz(m);
            }
        }
        if (lane == 0) {
            int lo = 0, hi = 0;
            if (mn >= 0) {
                float mnf = (float)mn, mxf = (float)mx;
                float ctr = (mxf + mnf) * 0.5f;
                float e   = (mxf - mnf + 1.0f) * 0.5f * 1.2f;     // EXPAND
                lo = (int)fmaxf(0.0f, floorf(ctr - e));
                hi = (int)fminf((float)(S - 1), floorf(ctr + e)); // EXCLUSIVE
            }
            g_lo[bb][ax] = lo;
            g_hi[bb][ax] = hi;
        }
    }
}

// ---------------- kernel 2: weighted SSE, grid-stride, finalize + reset -----
// 1036 blocks x 256 threads = exactly one resident wave (7 blocks/SM at
// <=36 regs). Pure flat grid-stride: all blocks march in lockstep over the
// 4.096M float4 groups (~15.5 iters each) -> perfect balance, no tail.
__global__ __launch_bounds__(256, 7) void k_main(const float* __restrict__ pred,
                                                 const float* __restrict__ truth,
                                                 float* __restrict__ out) {
    __shared__ int sLo[NB * 3];
    __shared__ int sHi[NB * 3];
    __shared__ double warpSum[8];
    __shared__ int sLast;

    const int tid = threadIdx.x;
    if (tid < NB * 3) {
        int bb = tid / 3, ax = tid - bb * 3;
        sLo[tid] = g_lo[bb][ax];
        sHi[tid] = g_hi[bb][ax];
    }
    __syncthreads();

    const float4* P = (const float4*)pred;
    const float4* T = (const float4*)truth;
    const int stride = gridDim.x * 256;             // 265,216
    float acc = 0.0f;

    #pragma unroll 4
    for (int j = blockIdx.x * 256 + tid; j < N4; j += stride) {
        float4 p = P[j];
        float4 t = T[j];

        int b    = j / BATCH4;
        int rem  = j - b * BATCH4;
        int d    = rem / PLANE4;
        int ip   = rem - d * PLANE4;
        int h    = ip / 40;
        int w0   = (ip - h * 40) * 4;
        int base = b * 3;

        bool inD = (d >= sLo[base + 0]) && (d < sHi[base + 0]);
        bool inH = inD && (h >= sLo[base + 1]) && (h < sHi[base + 1]);
        int loW = sLo[base + 2], hiW = sHi[base + 2];

        float wx = (inH && (w0 + 0) >= loW && (w0 + 0) < hiW) ? 1.0f : 0.01f;
        float wy = (inH && (w0 + 1) >= loW && (w0 + 1) < hiW) ? 1.0f : 0.01f;
        float wz = (inH && (w0 + 2) >= loW && (w0 + 2) < hiW) ? 1.0f : 0.01f;
        float ww = (inH && (w0 + 3) >= loW && (w0 + 3) < hiW) ? 1.0f : 0.01f;

        float dx = p.x - t.x, dy = p.y - t.y, dz = p.z - t.z, dw = p.w - t.w;
        acc = fmaf(wx * dx, dx, acc);
        acc = fmaf(wy * dy, dy, acc);
        acc = fmaf(wz * dz, dz, acc);
        acc = fmaf(ww * dw, dw, acc);
    }

    // warp reduce (float), block reduce (double), one atomicAdd per block
    #pragma unroll
    for (int off = 16; off > 0; off >>= 1)
        acc += __shfl_xor_sync(0xFFFFFFFFu, acc, off);

    int lane = tid & 31, wid = tid >> 5;
    if (lane == 0) warpSum[wid] = (double)acc;
    __syncthreads();
    if (tid == 0) {
        double s = 0.0;
        #pragma unroll
        for (int w = 0; w < 8; w++) s += warpSum[w];
        atomicAdd(&g_acc, s);
        __threadfence();
        unsigned ticket = atomicAdd(&g_done_main, 1u);
        sLast = (ticket == (unsigned)(gridDim.x - 1));
    }
    __syncthreads();

    // ---- last block: write result, then reset ALL scratch for next replay --
    if (sLast) {
        if (tid == 0) {
            double total = atomicAdd(&g_acc, 0.0);   // atomic read-after-all-adds
            out[0] = (float)(total / TOTAL_ELEMS);
            g_acc = 0.0;
            g_done_proj = 0u;
            g_done_main = 0u;
        }
        int* pz = (int*)g_any;                       // 1920 bytes = 480 ints
        for (int i = tid; i < (NB * 3 * S) / 4; i += 256) pz[i] = 0;
    }
}

extern "C" void kernel_launch(void* const* d_in, const int* in_sizes, int n_in,
                              void* d_out, int out_size) {
    const float* y_pred = (const float*)d_in[0];
    const float* y_true = (const float*)d_in[1];
    const int*   mask   = (const int*)d_in[2];
    float* out = (float*)d_out;

    k_proj<<<NPLANES, 320>>>(mask);
    k_main<<<MAIN_BLOCKS, 256>>>(y_pred, y_true, out);
}

// round 6
// speedup vs baseline: 1.1126x; 1.0566x over previous
#include <cuda_runtime.h>
#include <cuda_bf16.h>

// Problem geometry: [B=4, 1, D=160, H=160, W=160]
#define NB 4
#define S  160
#define PLANE4   6400              // float4/int4 per (b,d) plane
#define NPLANES  640
#define CHUNKS   5120              // 8 chunks per plane, 20 rows each
#define CHUNK4   800               // float4 per chunk (20 rows * 40)
#define NBLOCKS  (148 * 12)        // 1776 blocks, 160 threads: 12/SM -> 93.75% occ
#define NTHREADS 160
#define TOTAL_ELEMS (4.0 * 160.0 * 160.0 * 160.0)

// ---- device scratch (zero at load; k_main's last block re-zeroes everything
//      so each graph replay starts identically — no init kernel) ----
__device__ unsigned char g_any[NB][3][S];  // axis projections: 0=D,1=H,2=W
__device__ int      g_lo[NB][3];
__device__ int      g_hi[NB][3];
__device__ double   g_acc;
__device__ unsigned g_done_proj;
__device__ unsigned g_done_main;

// ---------------- kernel 1: mask -> projections; last block -> bbox ---------
// Grid-stride over 5120 chunks (20 rows x 40 int4). Thread owns fixed column
// c = tid%40, row-group rg = tid/40; 5 loads per chunk at constant offsets.
// W-axis OR in a register; one conditional shared byte store per 16B feeds
// the per-chunk row flags. Global flag stores are benign races (all store 1).
__global__ __launch_bounds__(NTHREADS, 12) void k_proj(const int* __restrict__ mask) {
    __shared__ int4 sCol[4][40];
    __shared__ unsigned char sRow[20];
    __shared__ int sLast;

    const int tid = threadIdx.x;
    const int rg  = tid / 40;            // 0..3
    const int c   = tid % 40;

    for (int chunk = blockIdx.x; chunk < CHUNKS; chunk += NBLOCKS) {
        const int plane = chunk >> 3;
        const int part  = chunk & 7;
        const int b     = plane / S;
        const int d     = plane - b * S;
        const int4* M   = (const int4*)mask + plane * PLANE4 + part * CHUNK4 + tid;

        if (tid < 20) sRow[tid] = 0;
        __syncthreads();

        int4 colOr = make_int4(0, 0, 0, 0);
        #pragma unroll
        for (int k = 0; k < 5; k++) {
            int4 v = __ldcs(M + 160 * k);
            colOr.x |= v.x; colOr.y |= v.y; colOr.z |= v.z; colOr.w |= v.w;
            if (v.x | v.y | v.z | v.w) sRow[rg + 4 * k] = 1;
        }
        sCol[rg][c] = colOr;
        int planeAny = __syncthreads_or(colOr.x | colOr.y | colOr.z | colOr.w);

        if (tid < 40) {
            int4 o = sCol[0][tid];
            #pragma unroll
            for (int r2 = 1; r2 < 4; r2++) {
                int4 v = sCol[r2][tid];
                o.x |= v.x; o.y |= v.y; o.z |= v.z; o.w |= v.w;
            }
            if (o.x) g_any[b][2][tid * 4 + 0] = 1;
            if (o.y) g_any[b][2][tid * 4 + 1] = 1;
            if (o.z) g_any[b][2][tid * 4 + 2] = 1;
            if (o.w) g_any[b][2][tid * 4 + 3] = 1;
        }
        if (tid < 20 && sRow[tid]) g_any[b][1][part * 20 + tid] = 1;
        if (tid == 0 && planeAny)  g_any[b][0][d] = 1;
        __syncthreads();
    }

    // ---- last-done block computes the 12 bbox axis ranges (ballot scan) ----
    __threadfence();
    if (tid == 0) {
        unsigned ticket = atomicAdd(&g_done_proj, 1u);
        sLast = (ticket == (unsigned)(gridDim.x - 1));
    }
    __syncthreads();
    if (!sLast) return;
    __threadfence();

    const int wid  = tid >> 5;           // 0..4
    const int lane = tid & 31;
    for (int pair = wid; pair < NB * 3; pair += 5) {
        int bb = pair / 3;
        int ax = pair - bb * 3;
        volatile unsigned char* a = &g_any[bb][ax][0];
        int mn = -1, mx = -1;
        #pragma unroll
        for (int k = 0; k < 5; k++) {    // 5 ballots x 32 = 160 coords
            unsigned m = __ballot_sync(0xFFFFFFFFu, a[lane + 32 * k] != 0);
            if (m) {
                if (mn < 0) mn = 32 * k + __ffs(m) - 1;
                mx = 32 * k + 31 - __clz(m);
            }
        }
        if (lane == 0) {
            int lo = 0, hi = 0;
            if (mn >= 0) {
                float mnf = (float)mn, mxf = (float)mx;
                float ctr = (mxf + mnf) * 0.5f;
                float e   = (mxf - mnf + 1.0f) * 0.5f * 1.2f;     // EXPAND
                lo = (int)fmaxf(0.0f, floorf(ctr - e));
                hi = (int)fminf((float)(S - 1), floorf(ctr + e)); // EXCLUSIVE
            }
            g_lo[bb][ax] = lo;
            g_hi[bb][ax] = hi;
        }
    }
}

// ---------------- kernel 2: weighted SSE; last block finalizes + resets -----
// Same chunk decomposition. Thread's column c = tid%40 is fixed, so its four
// W-axis weights are a single LDS.128 from a precomputed [NB][40] float4
// table; the inner 5-iteration loop is 2 LDG.128 at constant offsets + one
// h-range compare + 4 selects + 12 FP ops.
__global__ __launch_bounds__(NTHREADS, 12) void k_main(const float* __restrict__ pred,
                                                       const float* __restrict__ truth,
                                                       float* __restrict__ out) {
    __shared__ float4 sW[NB][40];        // (inW ? 1 : 0.01) quad per (b, c)
    __shared__ int4   sBnd[NB];          // (loD, hiD, loH, hiH)
    __shared__ double warpSum[5];
    __shared__ int sLast;

    const int tid = threadIdx.x;
    const int rg  = tid / 40;            // 0..3
    const int c   = tid % 40;

    {   // build weight table: exactly 160 threads -> one (b,c) each
        int tb = rg;                     // tid/40 == batch index
        int loW = g_lo[tb][2], hiW = g_hi[tb][2];
        float4 wq;
        wq.x = (c * 4 + 0 >= loW && c * 4 + 0 < hiW) ? 1.0f : 0.01f;
        wq.y = (c * 4 + 1 >= loW && c * 4 + 1 < hiW) ? 1.0f : 0.01f;
        wq.z = (c * 4 + 2 >= loW && c * 4 + 2 < hiW) ? 1.0f : 0.01f;
        wq.w = (c * 4 + 3 >= loW && c * 4 + 3 < hiW) ? 1.0f : 0.01f;
        sW[tb][c] = wq;
        if (tid < NB)
            sBnd[tid] = make_int4(g_lo[tid][0], g_hi[tid][0],
                                  g_lo[tid][1], g_hi[tid][1]);
    }
    __syncthreads();

    float acc = 0.0f;
    for (int chunk = blockIdx.x; chunk < CHUNKS; chunk += NBLOCKS) {
        const int plane = chunk >> 3;
        const int part  = chunk & 7;
        const int b     = plane / S;
        const int d     = plane - b * S;
        const int base  = plane * PLANE4 + part * CHUNK4 + tid;
        const float4* P = (const float4*)pred  + base;
        const float4* T = (const float4*)truth + base;

        const int4 bnd = sBnd[b];
        const bool inD = (d >= bnd.x) && (d < bnd.y);
        const int  hb  = part * 20 + rg;
        const float4 wq = sW[b][c];

        #pragma unroll
        for (int k = 0; k < 5; k++) {
            float4 p = __ldcs(P + 160 * k);
            float4 t = __ldcs(T + 160 * k);
            int h = hb + 4 * k;
            bool inRow = inD && (h >= bnd.z) && (h < bnd.w);

            float wx = inRow ? wq.x : 0.01f;
            float wy = inRow ? wq.y : 0.01f;
            float wz = inRow ? wq.z : 0.01f;
            float ww = inRow ? wq.w : 0.01f;

            float dx = p.x - t.x, dy = p.y - t.y, dz = p.z - t.z, dw = p.w - t.w;
            acc = fmaf(wx * dx, dx, acc);
            acc = fmaf(wy * dy, dy, acc);
            acc = fmaf(wz * dz, dz, acc);
            acc = fmaf(ww * dw, dw, acc);
        }
    }

    // warp reduce (float), block reduce (double), one atomicAdd per block
    #pragma unroll
    for (int off = 16; off > 0; off >>= 1)
        acc += __shfl_xor_sync(0xFFFFFFFFu, acc, off);

    int lane = tid & 31, wid = tid >> 5;
    if (lane == 0) warpSum[wid] = (double)acc;
    __syncthreads();
    if (tid == 0) {
        double s = 0.0;
        #pragma unroll
        for (int w = 0; w < 5; w++) s += warpSum[w];
        atomicAdd(&g_acc, s);
        __threadfence();
        unsigned ticket = atomicAdd(&g_done_main, 1u);
        sLast = (ticket == (unsigned)(gridDim.x - 1));
    }
    __syncthreads();

    // ---- last block: write result, then reset ALL scratch for next replay --
    if (sLast) {
        if (tid == 0) {
            double total = atomicAdd(&g_acc, 0.0);   // read after all adds
            out[0] = (float)(total / TOTAL_ELEMS);
            g_acc = 0.0;
            g_done_proj = 0u;
            g_done_main = 0u;
        }
        int* pz = (int*)g_any;                       // 1920 bytes = 480 ints
        for (int i = tid; i < (NB * 3 * S) / 4; i += NTHREADS) pz[i] = 0;
    }
}

extern "C" void kernel_launch(void* const* d_in, const int* in_sizes, int n_in,
                              void* d_out, int out_size) {
    const float* y_pred = (const float*)d_in[0];
    const float* y_true = (const float*)d_in[1];
    const int*   mask   = (const int*)d_in[2];
    float* out = (float*)d_out;

    k_proj<<<NBLOCKS, NTHREADS>>>(mask);
    k_main<<<NBLOCKS, NTHREADS>>>(y_pred, y_true, out);
}